// round 2
// baseline (speedup 1.0000x reference)
#include <cuda_runtime.h>
#include <math.h>

#define OUTN 11008
#define INN  4096
#define MTOK 4096            // 2 * 2048 tokens
#define NTOT 45088768        // OUTN * INN
#define NCNT 1024

// ---------------- scratch (static device globals; no allocation) ----------------
__device__ float  g_wt[NTOT];           // transformed/clipped -> final weights (180MB)
__device__ float  g_xq[MTOK * INN];     // fake-quantized activations (64MB)
__device__ float  g_rowabs[OUTN];
__device__ double g_psum[OUTN];
__device__ double g_psumsq[OUTN];
__device__ int    g_pcnt[NCNT];
__device__ float  g_stats[4];           // [0]=mean, [1]=T=3*std, [2]=is_like flag

// ---------------- K0: kronecker transform + clip + row stats ----------------
// One block per output row o. Computes L^T @ W_o @ R (64x64), row min/max,
// sigmoid clip, row absmax of clipped, and per-row sum/sumsq (double).
__global__ __launch_bounds__(256) void k_transform(
    const float* __restrict__ W, const float* __restrict__ L,
    const float* __restrict__ R, const float* __restrict__ cmax,
    const float* __restrict__ cmin)
{
    __shared__ double sAd[2048];   // 16KB, aliased as float sA[4096]
    __shared__ float  sL[4096];
    __shared__ float  sR[4096];
    float* sA = (float*)sAd;

    const int o   = blockIdx.x;
    const int tid = threadIdx.x;
    const int u   = tid >> 4;      // 0..15 (row-tile)
    const int v   = tid & 15;      // 0..15 (col-tile)

    const float* Wo = W + (size_t)o * INN;
    for (int i = tid; i < 4096; i += 256) { sA[i] = Wo[i]; sL[i] = L[i]; sR[i] = R[i]; }
    __syncthreads();

    // t[a,d] = sum_b W[a,b] * R[b,d]   (each thread: 4x4 tile)
    float acc[4][4];
    #pragma unroll
    for (int j = 0; j < 4; j++)
        #pragma unroll
        for (int l = 0; l < 4; l++) acc[j][l] = 0.f;

    for (int b = 0; b < 64; b++) {
        float4 rr = *(const float4*)&sR[(b << 6) + (v << 2)];
        float  wr[4];
        #pragma unroll
        for (int j = 0; j < 4; j++) wr[j] = sA[(((u << 2) + j) << 6) + b];
        #pragma unroll
        for (int j = 0; j < 4; j++) {
            acc[j][0] = fmaf(wr[j], rr.x, acc[j][0]);
            acc[j][1] = fmaf(wr[j], rr.y, acc[j][1]);
            acc[j][2] = fmaf(wr[j], rr.z, acc[j][2]);
            acc[j][3] = fmaf(wr[j], rr.w, acc[j][3]);
        }
    }
    __syncthreads();
    #pragma unroll
    for (int j = 0; j < 4; j++) {
        float4 t4 = make_float4(acc[j][0], acc[j][1], acc[j][2], acc[j][3]);
        *(float4*)&sA[(((u << 2) + j) << 6) + (v << 2)] = t4;   // sA now holds t
    }
    __syncthreads();

    // out[c,d] = sum_a L[a,c] * t[a,d]
    float vv[4][4];
    #pragma unroll
    for (int j = 0; j < 4; j++)
        #pragma unroll
        for (int l = 0; l < 4; l++) vv[j][l] = 0.f;

    for (int a = 0; a < 64; a++) {
        float4 td = *(const float4*)&sA[(a << 6) + (v << 2)];
        float4 lc = *(const float4*)&sL[(a << 6) + (u << 2)];
        float lcr[4] = {lc.x, lc.y, lc.z, lc.w};
        #pragma unroll
        for (int j = 0; j < 4; j++) {
            vv[j][0] = fmaf(lcr[j], td.x, vv[j][0]);
            vv[j][1] = fmaf(lcr[j], td.y, vv[j][1]);
            vv[j][2] = fmaf(lcr[j], td.z, vv[j][2]);
            vv[j][3] = fmaf(lcr[j], td.w, vv[j][3]);
        }
    }

    float lmin = 3.4e38f, lmax = -3.4e38f;
    #pragma unroll
    for (int j = 0; j < 4; j++)
        #pragma unroll
        for (int l = 0; l < 4; l++) { lmin = fminf(lmin, vv[j][l]); lmax = fmaxf(lmax, vv[j][l]); }

    __syncthreads();
    sR[tid] = lmin; sR[256 + tid] = lmax;
    __syncthreads();
    for (int s = 128; s > 0; s >>= 1) {
        if (tid < s) {
            sR[tid]       = fminf(sR[tid], sR[tid + s]);
            sR[256 + tid] = fmaxf(sR[256 + tid], sR[256 + tid + s]);
        }
        __syncthreads();
    }
    const float rmin = sR[0], rmax = sR[256];
    const float sgn_lo = 1.f / (1.f + expf(-cmin[o]));
    const float sgn_hi = 1.f / (1.f + expf(-cmax[o]));
    const float lo = rmin * sgn_lo;
    const float hi = rmax * sgn_hi;

    float la = 0.f; double ls = 0.0, lss = 0.0;
    #pragma unroll
    for (int j = 0; j < 4; j++)
        #pragma unroll
        for (int l = 0; l < 4; l++) {
            float w = fminf(fmaxf(vv[j][l], lo), hi);
            vv[j][l] = w;
            la = fmaxf(la, fabsf(w));
            ls += (double)w;
            lss += (double)w * (double)w;
        }

    __syncthreads();
    sAd[tid] = ls; sAd[256 + tid] = lss; sR[tid] = la;
    __syncthreads();
    for (int s = 128; s > 0; s >>= 1) {
        if (tid < s) {
            sAd[tid]       += sAd[tid + s];
            sAd[256 + tid] += sAd[256 + tid + s];
            sR[tid] = fmaxf(sR[tid], sR[tid + s]);
        }
        __syncthreads();
    }
    if (tid == 0) { g_psum[o] = sAd[0]; g_psumsq[o] = sAd[256]; g_rowabs[o] = sR[0]; }

    float* outp = g_wt + (size_t)o * INN;
    #pragma unroll
    for (int j = 0; j < 4; j++) {
        float4 c4 = make_float4(vv[j][0], vv[j][1], vv[j][2], vv[j][3]);
        *(float4*)&outp[(((u << 2) + j) << 6) + (v << 2)] = c4;
    }
}

// ---------------- K1: reduce per-row partials -> mean, T ----------------
__global__ __launch_bounds__(256) void k_stats1()
{
    __shared__ double ds[512];
    int tid = threadIdx.x;
    double s = 0.0, ss = 0.0;
    for (int i = tid; i < OUTN; i += 256) { s += g_psum[i]; ss += g_psumsq[i]; }
    ds[tid] = s; ds[256 + tid] = ss;
    __syncthreads();
    for (int st = 128; st > 0; st >>= 1) {
        if (tid < st) { ds[tid] += ds[tid + st]; ds[256 + tid] += ds[256 + tid + st]; }
        __syncthreads();
    }
    if (tid == 0) {
        double mean = ds[0] / (double)NTOT;
        double var  = ds[256] / (double)NTOT - mean * mean;
        if (var < 0.0) var = 0.0;
        g_stats[0] = (float)mean;
        g_stats[1] = (float)(3.0 * sqrt(var));
    }
}

// ---------------- K2: outlier count partials ----------------
__global__ __launch_bounds__(256) void k_count()
{
    const float mean = g_stats[0], T = g_stats[1];
    int cnt = 0;
    size_t stride = (size_t)gridDim.x * 256;
    for (size_t i = (size_t)blockIdx.x * 256 + threadIdx.x; i < (size_t)NTOT; i += stride)
        cnt += (fabsf(g_wt[i] - mean) > T) ? 1 : 0;
    __shared__ int sc[256];
    sc[threadIdx.x] = cnt;
    __syncthreads();
    for (int s = 128; s > 0; s >>= 1) {
        if (threadIdx.x < s) sc[threadIdx.x] += sc[threadIdx.x + s];
        __syncthreads();
    }
    if (threadIdx.x == 0) g_pcnt[blockIdx.x] = sc[0];
}

// ---------------- K3: finalize frac -> is_like ----------------
__global__ __launch_bounds__(1024) void k_frac()
{
    __shared__ int sc[NCNT];
    int tid = threadIdx.x;
    sc[tid] = g_pcnt[tid];
    __syncthreads();
    for (int s = 512; s > 0; s >>= 1) {
        if (tid < s) sc[tid] += sc[tid + s];
        __syncthreads();
    }
    if (tid == 0) {
        float frac = (float)sc[0] / (float)NTOT;
        g_stats[2] = (frac > 1e-4f && frac < 0.05f) ? 1.f : 0.f;
    }
}

// ---------------- K4: fold -> fake-quant -> unfold (in place) ----------------
__device__ __forceinline__ float wfinal_one(float w, float T, float scale, bool like, float a1)
{
    bool tg = like && (fabsf(w) > T);
    float win = tg ? copysignf(T + (fabsf(w) - T) * a1, w) : w;
    float q = rintf(win / scale);
    q = fminf(fmaxf(q, -7.f), 7.f);
    float wq = q * scale;
    return tg ? copysignf(T + (fabsf(wq) - T) / a1, w) : wq;
}

__global__ __launch_bounds__(256) void k_wfinal()
{
    const float a1 = 1.0f - 0.99f;
    size_t i4 = (size_t)blockIdx.x * 256 + threadIdx.x;
    if (i4 >= (size_t)NTOT / 4) return;
    size_t base = i4 * 4;
    int row = (int)(base >> 12);

    const float T = g_stats[1];
    const bool like = (g_stats[2] != 0.f);
    float ra = g_rowabs[row];
    float m = (like && ra > T) ? (T + (ra - T) * a1) : ra;   // fold is monotone in |w|
    float scale = m / 7.0f + 1e-8f;

    float4 w4 = *(const float4*)(g_wt + base);
    w4.x = wfinal_one(w4.x, T, scale, like, a1);
    w4.y = wfinal_one(w4.y, T, scale, like, a1);
    w4.z = wfinal_one(w4.z, T, scale, like, a1);
    w4.w = wfinal_one(w4.w, T, scale, like, a1);
    *(float4*)(g_wt + base) = w4;
}

// ---------------- K5: per-token activation fake-quant ----------------
__global__ __launch_bounds__(256) void k_actq(const float* __restrict__ X)
{
    __shared__ float red[256];
    int t = blockIdx.x, tid = threadIdx.x;
    const float* x = X + (size_t)t * INN;
    float4 vals[4];
    float la = 0.f;
    #pragma unroll
    for (int i = 0; i < 4; i++) {
        vals[i] = *(const float4*)&x[(tid + i * 256) * 4];
        la = fmaxf(la, fmaxf(fmaxf(fabsf(vals[i].x), fabsf(vals[i].y)),
                             fmaxf(fabsf(vals[i].z), fabsf(vals[i].w))));
    }
    red[tid] = la;
    __syncthreads();
    for (int s = 128; s > 0; s >>= 1) {
        if (tid < s) red[tid] = fmaxf(red[tid], red[tid + s]);
        __syncthreads();
    }
    const float scale = red[0] / 127.0f + 1e-8f;
    float* out = g_xq + (size_t)t * INN;
    #pragma unroll
    for (int i = 0; i < 4; i++) {
        float4 v = vals[i];
        float q;
        q = fminf(fmaxf(rintf(v.x / scale), -127.f), 127.f); v.x = q * scale;
        q = fminf(fmaxf(rintf(v.y / scale), -127.f), 127.f); v.y = q * scale;
        q = fminf(fmaxf(rintf(v.z / scale), -127.f), 127.f); v.z = q * scale;
        q = fminf(fmaxf(rintf(v.w / scale), -127.f), 127.f); v.w = q * scale;
        *(float4*)&out[(tid + i * 256) * 4] = v;
    }
}

// ---------------- K6: SGEMM out[m,n] = sum_k xq[m,k]*wf[n,k] + bias[n] ----------------
__global__ __launch_bounds__(256) void k_gemm(const float* __restrict__ bias, float* __restrict__ C)
{
    __shared__ float As[8][128];
    __shared__ float Bs[8][128];
    const float* A = g_xq;   // M x K
    const float* B = g_wt;   // N x K
    const int bn = blockIdx.x * 128;
    const int bm = blockIdx.y * 128;
    const int tid = threadIdx.x;
    const int tx = tid & 15, ty = tid >> 4;
    const int lrow = tid >> 1;
    const int lcol = (tid & 1) * 4;

    const float* Ap = A + (size_t)(bm + lrow) * INN + lcol;
    const float* Bp = B + (size_t)(bn + lrow) * INN + lcol;

    float acc[8][8];
    #pragma unroll
    for (int i = 0; i < 8; i++)
        #pragma unroll
        for (int j = 0; j < 8; j++) acc[i][j] = 0.f;

    for (int k0 = 0; k0 < INN; k0 += 8) {
        float4 av = *(const float4*)(Ap + k0);
        float4 bv = *(const float4*)(Bp + k0);
        __syncthreads();
        As[lcol + 0][lrow] = av.x; As[lcol + 1][lrow] = av.y;
        As[lcol + 2][lrow] = av.z; As[lcol + 3][lrow] = av.w;
        Bs[lcol + 0][lrow] = bv.x; Bs[lcol + 1][lrow] = bv.y;
        Bs[lcol + 2][lrow] = bv.z; Bs[lcol + 3][lrow] = bv.w;
        __syncthreads();
        #pragma unroll
        for (int k = 0; k < 8; k++) {
            float4 a0 = *(const float4*)&As[k][ty * 8];
            float4 a1 = *(const float4*)&As[k][ty * 8 + 4];
            float4 b0 = *(const float4*)&Bs[k][tx * 8];
            float4 b1 = *(const float4*)&Bs[k][tx * 8 + 4];
            float ar[8] = {a0.x, a0.y, a0.z, a0.w, a1.x, a1.y, a1.z, a1.w};
            float br[8] = {b0.x, b0.y, b0.z, b0.w, b1.x, b1.y, b1.z, b1.w};
            #pragma unroll
            for (int i = 0; i < 8; i++)
                #pragma unroll
                for (int j = 0; j < 8; j++)
                    acc[i][j] = fmaf(ar[i], br[j], acc[i][j]);
        }
    }

    float bb[8];
    #pragma unroll
    for (int j = 0; j < 8; j++) bb[j] = bias[bn + tx * 8 + j];

    #pragma unroll
    for (int i = 0; i < 8; i++) {
        int m = bm + ty * 8 + i;
        float* crow = C + (size_t)m * OUTN + bn + tx * 8;
        float4 o0 = make_float4(acc[i][0] + bb[0], acc[i][1] + bb[1],
                                acc[i][2] + bb[2], acc[i][3] + bb[3]);
        float4 o1 = make_float4(acc[i][4] + bb[4], acc[i][5] + bb[5],
                                acc[i][6] + bb[6], acc[i][7] + bb[7]);
        *(float4*)crow = o0;
        *(float4*)(crow + 4) = o1;
    }
}

// ---------------- launch ----------------
extern "C" void kernel_launch(void* const* d_in, const int* in_sizes, int n_in,
                              void* d_out, int out_size)
{
    const float* hs   = (const float*)d_in[0];  // (2,2048,4096)
    const float* w    = (const float*)d_in[1];  // (11008,4096)
    const float* bias = (const float*)d_in[2];  // (11008)
    const float* tl   = (const float*)d_in[3];  // (64,64)
    const float* tr   = (const float*)d_in[4];  // (64,64)
    const float* cmax = (const float*)d_in[5];  // (11008,1)
    const float* cmin = (const float*)d_in[6];  // (11008,1)
    float* out = (float*)d_out;

    k_transform<<<OUTN, 256>>>(w, tl, tr, cmax, cmin);
    k_stats1<<<1, 256>>>();
    k_count<<<NCNT, 256>>>();
    k_frac<<<1, 1024>>>();
    k_wfinal<<<(NTOT / 4 + 255) / 256, 256>>>();
    k_actq<<<MTOK, 256>>>(hs);
    dim3 g(OUTN / 128, MTOK / 128);
    k_gemm<<<g, 256>>>(bias, out);
}

// round 3
// speedup vs baseline: 2.1871x; 2.1871x over previous
#include <cuda_runtime.h>
#include <cuda_bf16.h>
#include <math.h>

#define OUTN 11008
#define INN  4096
#define MTOK 4096            // 2 * 2048 tokens
#define NTOT 45088768        // OUTN * INN
#define NCNT 1024

// ---------------- scratch (static device globals; no allocation) ----------------
__device__ float         g_wt[NTOT];          // transformed/clipped weights (fp32, 180MB)
__device__ __nv_bfloat16 g_bhi[NTOT];         // bf16 hi of final weights (90MB)
__device__ __nv_bfloat16 g_blo[NTOT];         // bf16 lo residual (90MB)
__device__ __nv_bfloat16 g_xb[MTOK * INN];    // bf16 integer activations q (32MB)
__device__ float         g_ascale[MTOK];      // per-token act scale
__device__ float         g_rowabs[OUTN];
__device__ double        g_psum[OUTN];
__device__ double        g_psumsq[OUTN];
__device__ int           g_pcnt[NCNT];
__device__ float         g_stats[4];          // [0]=mean, [1]=T=3*std, [2]=is_like

// ---------------- K0: kronecker transform + clip + row stats ----------------
__global__ __launch_bounds__(256) void k_transform(
    const float* __restrict__ W, const float* __restrict__ L,
    const float* __restrict__ R, const float* __restrict__ cmax,
    const float* __restrict__ cmin)
{
    __shared__ double sAd[2048];   // 16KB, aliased as float sA[4096]
    __shared__ float  sL[4096];
    __shared__ float  sR[4096];
    float* sA = (float*)sAd;

    const int o   = blockIdx.x;
    const int tid = threadIdx.x;
    const int u   = tid >> 4;
    const int v   = tid & 15;

    const float* Wo = W + (size_t)o * INN;
    for (int i = tid; i < 4096; i += 256) { sA[i] = Wo[i]; sL[i] = L[i]; sR[i] = R[i]; }
    __syncthreads();

    float acc[4][4];
    #pragma unroll
    for (int j = 0; j < 4; j++)
        #pragma unroll
        for (int l = 0; l < 4; l++) acc[j][l] = 0.f;

    for (int b = 0; b < 64; b++) {
        float4 rr = *(const float4*)&sR[(b << 6) + (v << 2)];
        float  wr[4];
        #pragma unroll
        for (int j = 0; j < 4; j++) wr[j] = sA[(((u << 2) + j) << 6) + b];
        #pragma unroll
        for (int j = 0; j < 4; j++) {
            acc[j][0] = fmaf(wr[j], rr.x, acc[j][0]);
            acc[j][1] = fmaf(wr[j], rr.y, acc[j][1]);
            acc[j][2] = fmaf(wr[j], rr.z, acc[j][2]);
            acc[j][3] = fmaf(wr[j], rr.w, acc[j][3]);
        }
    }
    __syncthreads();
    #pragma unroll
    for (int j = 0; j < 4; j++)
        *(float4*)&sA[(((u << 2) + j) << 6) + (v << 2)] =
            make_float4(acc[j][0], acc[j][1], acc[j][2], acc[j][3]);
    __syncthreads();

    float vv[4][4];
    #pragma unroll
    for (int j = 0; j < 4; j++)
        #pragma unroll
        for (int l = 0; l < 4; l++) vv[j][l] = 0.f;

    for (int a = 0; a < 64; a++) {
        float4 td = *(const float4*)&sA[(a << 6) + (v << 2)];
        float4 lc = *(const float4*)&sL[(a << 6) + (u << 2)];
        float lcr[4] = {lc.x, lc.y, lc.z, lc.w};
        #pragma unroll
        for (int j = 0; j < 4; j++) {
            vv[j][0] = fmaf(lcr[j], td.x, vv[j][0]);
            vv[j][1] = fmaf(lcr[j], td.y, vv[j][1]);
            vv[j][2] = fmaf(lcr[j], td.z, vv[j][2]);
            vv[j][3] = fmaf(lcr[j], td.w, vv[j][3]);
        }
    }

    float lmin = 3.4e38f, lmax = -3.4e38f;
    #pragma unroll
    for (int j = 0; j < 4; j++)
        #pragma unroll
        for (int l = 0; l < 4; l++) { lmin = fminf(lmin, vv[j][l]); lmax = fmaxf(lmax, vv[j][l]); }

    __syncthreads();
    sR[tid] = lmin; sR[256 + tid] = lmax;
    __syncthreads();
    for (int s = 128; s > 0; s >>= 1) {
        if (tid < s) {
            sR[tid]       = fminf(sR[tid], sR[tid + s]);
            sR[256 + tid] = fmaxf(sR[256 + tid], sR[256 + tid + s]);
        }
        __syncthreads();
    }
    const float rmin = sR[0], rmax = sR[256];
    const float lo = rmin * (1.f / (1.f + expf(-cmin[o])));
    const float hi = rmax * (1.f / (1.f + expf(-cmax[o])));

    float la = 0.f; double ls = 0.0, lss = 0.0;
    #pragma unroll
    for (int j = 0; j < 4; j++)
        #pragma unroll
        for (int l = 0; l < 4; l++) {
            float w = fminf(fmaxf(vv[j][l], lo), hi);
            vv[j][l] = w;
            la = fmaxf(la, fabsf(w));
            ls += (double)w;
            lss += (double)w * (double)w;
        }

    __syncthreads();
    sAd[tid] = ls; sAd[256 + tid] = lss; sR[tid] = la;
    __syncthreads();
    for (int s = 128; s > 0; s >>= 1) {
        if (tid < s) {
            sAd[tid]       += sAd[tid + s];
            sAd[256 + tid] += sAd[256 + tid + s];
            sR[tid] = fmaxf(sR[tid], sR[tid + s]);
        }
        __syncthreads();
    }
    if (tid == 0) { g_psum[o] = sAd[0]; g_psumsq[o] = sAd[256]; g_rowabs[o] = sR[0]; }

    float* outp = g_wt + (size_t)o * INN;
    #pragma unroll
    for (int j = 0; j < 4; j++)
        *(float4*)&outp[(((u << 2) + j) << 6) + (v << 2)] =
            make_float4(vv[j][0], vv[j][1], vv[j][2], vv[j][3]);
}

// ---------------- K1: reduce per-row partials -> mean, T ----------------
__global__ __launch_bounds__(256) void k_stats1()
{
    __shared__ double ds[512];
    int tid = threadIdx.x;
    double s = 0.0, ss = 0.0;
    for (int i = tid; i < OUTN; i += 256) { s += g_psum[i]; ss += g_psumsq[i]; }
    ds[tid] = s; ds[256 + tid] = ss;
    __syncthreads();
    for (int st = 128; st > 0; st >>= 1) {
        if (tid < st) { ds[tid] += ds[tid + st]; ds[256 + tid] += ds[256 + tid + st]; }
        __syncthreads();
    }
    if (tid == 0) {
        double mean = ds[0] / (double)NTOT;
        double var  = ds[256] / (double)NTOT - mean * mean;
        if (var < 0.0) var = 0.0;
        g_stats[0] = (float)mean;
        g_stats[1] = (float)(3.0 * sqrt(var));
    }
}

// ---------------- K2: outlier count partials ----------------
__global__ __launch_bounds__(256) void k_count()
{
    const float mean = g_stats[0], T = g_stats[1];
    int cnt = 0;
    size_t stride = (size_t)gridDim.x * 256 * 4;
    for (size_t i = ((size_t)blockIdx.x * 256 + threadIdx.x) * 4; i < (size_t)NTOT; i += stride) {
        float4 w4 = *(const float4*)(g_wt + i);
        cnt += (fabsf(w4.x - mean) > T) + (fabsf(w4.y - mean) > T)
             + (fabsf(w4.z - mean) > T) + (fabsf(w4.w - mean) > T);
    }
    __shared__ int sc[256];
    sc[threadIdx.x] = cnt;
    __syncthreads();
    for (int s = 128; s > 0; s >>= 1) {
        if (threadIdx.x < s) sc[threadIdx.x] += sc[threadIdx.x + s];
        __syncthreads();
    }
    if (threadIdx.x == 0) g_pcnt[blockIdx.x] = sc[0];
}

// ---------------- K3: finalize frac -> is_like ----------------
__global__ __launch_bounds__(1024) void k_frac()
{
    __shared__ int sc[NCNT];
    int tid = threadIdx.x;
    sc[tid] = g_pcnt[tid];
    __syncthreads();
    for (int s = 512; s > 0; s >>= 1) {
        if (tid < s) sc[tid] += sc[tid + s];
        __syncthreads();
    }
    if (tid == 0) {
        float frac = (float)sc[0] / (float)NTOT;
        g_stats[2] = (frac > 1e-4f && frac < 0.05f) ? 1.f : 0.f;
    }
}

// ---------------- K4: fold -> fake-quant -> unfold -> bf16 hi/lo split ----------------
__device__ __forceinline__ float wfinal_one(float w, float T, float scale, bool like, float a1)
{
    bool tg = like && (fabsf(w) > T);
    float win = tg ? copysignf(T + (fabsf(w) - T) * a1, w) : w;
    float q = rintf(win / scale);
    q = fminf(fmaxf(q, -7.f), 7.f);
    float wq = q * scale;
    return tg ? copysignf(T + (fabsf(wq) - T) / a1, w) : wq;
}

__global__ __launch_bounds__(256) void k_wfinal()
{
    const float a1 = 1.0f - 0.99f;
    size_t i4 = (size_t)blockIdx.x * 256 + threadIdx.x;
    if (i4 >= (size_t)NTOT / 4) return;
    size_t base = i4 * 4;
    int row = (int)(base >> 12);

    const float T = g_stats[1];
    const bool like = (g_stats[2] != 0.f);
    float ra = g_rowabs[row];
    float m = (like && ra > T) ? (T + (ra - T) * a1) : ra;   // fold monotone in |w|
    float scale = m / 7.0f + 1e-8f;

    float4 w4 = *(const float4*)(g_wt + base);
    float wf[4];
    wf[0] = wfinal_one(w4.x, T, scale, like, a1);
    wf[1] = wfinal_one(w4.y, T, scale, like, a1);
    wf[2] = wfinal_one(w4.z, T, scale, like, a1);
    wf[3] = wfinal_one(w4.w, T, scale, like, a1);

    __nv_bfloat16 hi[4], lo[4];
    #pragma unroll
    for (int j = 0; j < 4; j++) {
        hi[j] = __float2bfloat16_rn(wf[j]);
        lo[j] = __float2bfloat16_rn(wf[j] - __bfloat162float(hi[j]));
    }
    *(uint2*)(g_bhi + base) = *(uint2*)hi;
    *(uint2*)(g_blo + base) = *(uint2*)lo;
}

// ---------------- K5: per-token activation fake-quant (-> bf16 ints + scale) ----------------
__global__ __launch_bounds__(256) void k_actq(const float* __restrict__ X)
{
    __shared__ float red[256];
    int t = blockIdx.x, tid = threadIdx.x;
    const float* x = X + (size_t)t * INN;
    float4 vals[4];
    float la = 0.f;
    #pragma unroll
    for (int i = 0; i < 4; i++) {
        vals[i] = *(const float4*)&x[(tid + i * 256) * 4];
        la = fmaxf(la, fmaxf(fmaxf(fabsf(vals[i].x), fabsf(vals[i].y)),
                             fmaxf(fabsf(vals[i].z), fabsf(vals[i].w))));
    }
    red[tid] = la;
    __syncthreads();
    for (int s = 128; s > 0; s >>= 1) {
        if (tid < s) red[tid] = fmaxf(red[tid], red[tid + s]);
        __syncthreads();
    }
    const float scale = red[0] / 127.0f + 1e-8f;
    if (tid == 0) g_ascale[t] = scale;
    __nv_bfloat16* out = g_xb + (size_t)t * INN;
    #pragma unroll
    for (int i = 0; i < 4; i++) {
        float4 v = vals[i];
        __nv_bfloat16 q4[4];
        q4[0] = __float2bfloat16_rn(fminf(fmaxf(rintf(v.x / scale), -127.f), 127.f));
        q4[1] = __float2bfloat16_rn(fminf(fmaxf(rintf(v.y / scale), -127.f), 127.f));
        q4[2] = __float2bfloat16_rn(fminf(fmaxf(rintf(v.z / scale), -127.f), 127.f));
        q4[3] = __float2bfloat16_rn(fminf(fmaxf(rintf(v.w / scale), -127.f), 127.f));
        *(uint2*)&out[(tid + i * 256) * 4] = *(uint2*)q4;
    }
}

// ---------------- K6: bf16 tensor-core GEMM (split-K over hi/lo weights) ----------------
// C[m,n] = ascale[m] * sum_k q[m,k]*(whi[n,k]+wlo[n,k]) + bias[n]
#define BK   32
#define SPAD 40      // smem row stride (elems): 80B -> conflict-free ldmatrix phases
#define KITERS 256   // 2 * INN / BK

__device__ __forceinline__ void cpasync16(unsigned saddr, const void* g)
{
    asm volatile("cp.async.ca.shared.global [%0], [%1], 16;\n" :: "r"(saddr), "l"(g));
}
__device__ __forceinline__ void ldsm4(unsigned* r, unsigned saddr)
{
    asm volatile("ldmatrix.sync.aligned.m8n8.x4.shared.b16 {%0,%1,%2,%3}, [%4];"
                 : "=r"(r[0]), "=r"(r[1]), "=r"(r[2]), "=r"(r[3]) : "r"(saddr));
}
__device__ __forceinline__ void mma16816(float* d, const unsigned* a, unsigned b0, unsigned b1)
{
    asm volatile("mma.sync.aligned.m16n8k16.row.col.f32.bf16.bf16.f32 "
                 "{%0,%1,%2,%3}, {%4,%5,%6,%7}, {%8,%9}, {%0,%1,%2,%3};"
                 : "+f"(d[0]), "+f"(d[1]), "+f"(d[2]), "+f"(d[3])
                 : "r"(a[0]), "r"(a[1]), "r"(a[2]), "r"(a[3]), "r"(b0), "r"(b1));
}

__global__ __launch_bounds__(256) void k_gemm_t(const float* __restrict__ bias,
                                                float* __restrict__ C)
{
    __shared__ __nv_bfloat16 sA[2][128 * SPAD];
    __shared__ __nv_bfloat16 sB[2][128 * SPAD];

    const int tid  = threadIdx.x;
    const int lane = tid & 31;
    const int wid  = tid >> 5;
    const int wm   = wid & 1;       // 2 warps in M
    const int wn   = wid >> 1;      // 4 warps in N
    const int bn   = blockIdx.x * 128;
    const int bm   = blockIdx.y * 128;

    const int lrow = tid >> 2;          // 0..63
    const int lcol = (tid & 3) * 8;     // 0,8,16,24

    float acc[4][4][4];
    #pragma unroll
    for (int i = 0; i < 4; i++)
        #pragma unroll
        for (int j = 0; j < 4; j++)
            #pragma unroll
            for (int l = 0; l < 4; l++) acc[i][j][l] = 0.f;

    const __nv_bfloat16* Abase = g_xb + (size_t)bm * INN;

    // ---- tile loader ----
    auto load_tile = [&](int it, int buf) {
        int kv = it * BK;
        int ka = kv & (INN - 1);
        const __nv_bfloat16* Bsel = (kv < INN) ? g_bhi : g_blo;
        int kb = kv & (INN - 1);
        const __nv_bfloat16* Bp = Bsel + (size_t)bn * INN + kb;
        #pragma unroll
        for (int i = 0; i < 2; i++) {
            int row = lrow + i * 64;
            cpasync16((unsigned)__cvta_generic_to_shared(&sA[buf][row * SPAD + lcol]),
                      Abase + (size_t)row * INN + ka + lcol);
            cpasync16((unsigned)__cvta_generic_to_shared(&sB[buf][row * SPAD + lcol]),
                      Bp + (size_t)row * INN + lcol);
        }
    };

    load_tile(0, 0);
    asm volatile("cp.async.commit_group;\n");

    for (int it = 0; it < KITERS; ++it) {
        int buf = it & 1;
        if (it + 1 < KITERS) {
            load_tile(it + 1, buf ^ 1);
            asm volatile("cp.async.commit_group;\n");
            asm volatile("cp.async.wait_group 1;\n");
        } else {
            asm volatile("cp.async.wait_group 0;\n");
        }
        __syncthreads();

        #pragma unroll
        for (int ks = 0; ks < 2; ks++) {
            unsigned afr[4][4], bfr[2][4];
            int arow = wm * 64 + (lane & 15);
            int acol = ks * 16 + (lane >> 4) * 8;
            #pragma unroll
            for (int mb = 0; mb < 4; mb++)
                ldsm4(afr[mb], (unsigned)__cvta_generic_to_shared(
                          &sA[buf][(arow + mb * 16) * SPAD + acol]));
            int brow = wn * 32 + (lane & 7) + ((lane >> 4) & 1) * 8;
            int bcol = ks * 16 + ((lane >> 3) & 1) * 8;
            #pragma unroll
            for (int nb = 0; nb < 2; nb++)
                ldsm4(bfr[nb], (unsigned)__cvta_generic_to_shared(
                          &sB[buf][(brow + nb * 16) * SPAD + bcol]));
            #pragma unroll
            for (int mb = 0; mb < 4; mb++)
                #pragma unroll
                for (int f = 0; f < 4; f++)
                    mma16816(acc[mb][f], afr[mb],
                             bfr[f >> 1][(f & 1) * 2], bfr[f >> 1][(f & 1) * 2 + 1]);
        }
        __syncthreads();
    }

    // ---- epilogue: scale by ascale[m], add bias, store ----
    #pragma unroll
    for (int mb = 0; mb < 4; mb++) {
        int m0 = bm + wm * 64 + mb * 16 + (lane >> 2);
        float as0 = g_ascale[m0];
        float as1 = g_ascale[m0 + 8];
        #pragma unroll
        for (int f = 0; f < 4; f++) {
            int gn = bn + wn * 32 + f * 8 + (lane & 3) * 2;
            float b0 = bias[gn], b1 = bias[gn + 1];
            float2 o0 = make_float2(acc[mb][f][0] * as0 + b0, acc[mb][f][1] * as0 + b1);
            float2 o1 = make_float2(acc[mb][f][2] * as1 + b0, acc[mb][f][3] * as1 + b1);
            *(float2*)(C + (size_t)m0 * OUTN + gn)       = o0;
            *(float2*)(C + (size_t)(m0 + 8) * OUTN + gn) = o1;
        }
    }
}

// ---------------- launch ----------------
extern "C" void kernel_launch(void* const* d_in, const int* in_sizes, int n_in,
                              void* d_out, int out_size)
{
    const float* hs   = (const float*)d_in[0];  // (2,2048,4096)
    const float* w    = (const float*)d_in[1];  // (11008,4096)
    const float* bias = (const float*)d_in[2];  // (11008)
    const float* tl   = (const float*)d_in[3];  // (64,64)
    const float* tr   = (const float*)d_in[4];  // (64,64)
    const float* cmax = (const float*)d_in[5];  // (11008,1)
    const float* cmin = (const float*)d_in[6];  // (11008,1)
    float* out = (float*)d_out;

    k_transform<<<OUTN, 256>>>(w, tl, tr, cmax, cmin);
    k_stats1<<<1, 256>>>();
    k_count<<<NCNT, 256>>>();
    k_frac<<<1, 1024>>>();
    k_wfinal<<<(NTOT / 4 + 255) / 256, 256>>>();
    k_actq<<<MTOK, 256>>>(hs);
    dim3 g(OUTN / 128, MTOK / 128);
    k_gemm_t<<<g, 256>>>(bias, out);
}